// round 1
// baseline (speedup 1.0000x reference)
#include <cuda_runtime.h>
#include <cstdint>

#define N_NODES 100000
#define E_EDGES 1600000
#define DH 128
#define BN_EPS 1e-5f

// ---------------- scratch (static device memory; no allocations) ----------------
__device__ float g_bufH[(size_t)N_NODES * DH];
__device__ float g_bufA[(size_t)N_NODES * DH];
__device__ float g_bufB[(size_t)N_NODES * DH];
__device__ float g_deg[N_NODES];
__device__ float g_dinv[N_NODES];
__device__ float g_sum[DH];
__device__ float g_sumsq[DH];
__device__ float g_bnscale[DH];
__device__ float g_bnshift[DH];

// ---------------- small kernels ----------------
__global__ void init_deg_k(float* __restrict__ deg, float* __restrict__ sum,
                           float* __restrict__ sumsq) {
    int i = blockIdx.x * blockDim.x + threadIdx.x;
    if (i < N_NODES) deg[i] = 1.0f;               // self-loop
    if (i < DH) { sum[i] = 0.f; sumsq[i] = 0.f; }
}

__global__ void count_deg_k(const int* __restrict__ dst, float* __restrict__ deg) {
    int e = blockIdx.x * blockDim.x + threadIdx.x;
    if (e < E_EDGES) atomicAdd(&deg[dst[e]], 1.0f);
}

__global__ void dinv_k(const float* __restrict__ deg, float* __restrict__ dinv) {
    int i = blockIdx.x * blockDim.x + threadIdx.x;
    if (i < N_NODES) dinv[i] = rsqrtf(deg[i]);
}

// ---------------- GEMM: [N,128] @ [128,128], fused input transform ----------------
// MODE 0: A as-is          -> write H and Out = H*dinv^2 + b
// MODE 1: relu(A)          -> write H and Out = H*dinv^2 + b
// MODE 2: bn(relu(A))      -> write Out = relu(acc + b) only
template <int MODE>
__global__ void __launch_bounds__(256)
gemm128_k(const float* __restrict__ A, const float* __restrict__ W,
          const float* __restrict__ bias, float* __restrict__ H,
          float* __restrict__ Out, const float* __restrict__ dinv,
          const float* __restrict__ bnscale, const float* __restrict__ bnshift) {
    __shared__ float Ws[32][DH];
    __shared__ float As[32][33];

    const int tid = threadIdx.x;
    const int row0 = blockIdx.x * 32;
    const int ty = tid >> 5;   // 0..7  -> 4 rows each
    const int tx = tid & 31;   // 0..31 -> 4 cols each

    float acc[4][4] = {};

    const float4* W4 = (const float4*)W;

    for (int kt = 0; kt < 4; ++kt) {
        // load A tile 32x32 (coalesced), fused transform
        #pragma unroll
        for (int i = 0; i < 4; ++i) {
            int idx = tid + i * 256;
            int r = idx >> 5, k = idx & 31;
            int gcol = kt * 32 + k;
            float v = A[(size_t)(row0 + r) * DH + gcol];
            if (MODE >= 1) v = fmaxf(v, 0.f);
            if (MODE == 2) v = v * bnscale[gcol] + bnshift[gcol];
            As[r][k] = v;
        }
        // load W tile 32x128 via float4 (coalesced)
        #pragma unroll
        for (int i = 0; i < 4; ++i) {
            int idx = tid + i * 256;
            int kr = idx >> 5, n4 = idx & 31;
            float4 w = W4[(size_t)(kt * 32 + kr) * 32 + n4];
            *(float4*)&Ws[kr][n4 * 4] = w;
        }
        __syncthreads();

        #pragma unroll
        for (int k = 0; k < 32; ++k) {
            float a0 = As[ty * 4 + 0][k];
            float a1 = As[ty * 4 + 1][k];
            float a2 = As[ty * 4 + 2][k];
            float a3 = As[ty * 4 + 3][k];
            float4 b = *(float4*)&Ws[k][tx * 4];
            acc[0][0] += a0 * b.x; acc[0][1] += a0 * b.y; acc[0][2] += a0 * b.z; acc[0][3] += a0 * b.w;
            acc[1][0] += a1 * b.x; acc[1][1] += a1 * b.y; acc[1][2] += a1 * b.z; acc[1][3] += a1 * b.w;
            acc[2][0] += a2 * b.x; acc[2][1] += a2 * b.y; acc[2][2] += a2 * b.z; acc[2][3] += a2 * b.w;
            acc[3][0] += a3 * b.x; acc[3][1] += a3 * b.y; acc[3][2] += a3 * b.z; acc[3][3] += a3 * b.w;
        }
        __syncthreads();
    }

    float4 bv = *(const float4*)&bias[tx * 4];
    #pragma unroll
    for (int i = 0; i < 4; ++i) {
        int r = row0 + ty * 4 + i;
        if (MODE < 2) {
            float sc = dinv[r]; sc = sc * sc;
            float4 h = make_float4(acc[i][0], acc[i][1], acc[i][2], acc[i][3]);
            *(float4*)&H[(size_t)r * DH + tx * 4] = h;
            float4 o = make_float4(h.x * sc + bv.x, h.y * sc + bv.y,
                                   h.z * sc + bv.z, h.w * sc + bv.w);
            *(float4*)&Out[(size_t)r * DH + tx * 4] = o;
        } else {
            float4 o = make_float4(fmaxf(acc[i][0] + bv.x, 0.f),
                                   fmaxf(acc[i][1] + bv.y, 0.f),
                                   fmaxf(acc[i][2] + bv.z, 0.f),
                                   fmaxf(acc[i][3] + bv.w, 0.f));
            *(float4*)&Out[(size_t)r * DH + tx * 4] = o;
        }
    }
}

// ---------------- edge aggregation: warp per edge, vectorized reduction ----------
__device__ __forceinline__ void red4(float* p, float4 v) {
    asm volatile("red.global.add.v4.f32 [%0], {%1, %2, %3, %4};"
                 :: "l"(p), "f"(v.x), "f"(v.y), "f"(v.z), "f"(v.w)
                 : "memory");
}

__global__ void __launch_bounds__(256)
edge_agg_k(const int* __restrict__ src, const int* __restrict__ dst,
           const float* __restrict__ dinv, const float* __restrict__ H,
           float* __restrict__ Out) {
    int w = (blockIdx.x * blockDim.x + threadIdx.x) >> 5;
    if (w >= E_EDGES) return;
    int lane = threadIdx.x & 31;
    int s = __ldg(&src[w]);
    int d = __ldg(&dst[w]);
    float c = dinv[s] * dinv[d];
    float4 v = ((const float4*)(H + (size_t)s * DH))[lane];
    v.x *= c; v.y *= c; v.z *= c; v.w *= c;
    red4(Out + (size_t)d * DH + lane * 4, v);
}

// ---------------- BN statistics over relu(h), column-wise -----------------------
__global__ void __launch_bounds__(256)
bn_stats_k(const float* __restrict__ A, float* __restrict__ sum,
           float* __restrict__ sumsq) {
    const int col = threadIdx.x & 127;
    const int half = threadIdx.x >> 7;
    const int r0 = blockIdx.x * 800;
    float s = 0.f, q = 0.f;
    for (int r = r0 + half; r < r0 + 800; r += 2) {
        float v = fmaxf(A[(size_t)r * DH + col], 0.f);
        s += v; q += v * v;
    }
    __shared__ float sh[256];
    sh[threadIdx.x] = s; __syncthreads();
    if (half == 0) atomicAdd(&sum[col], sh[col] + sh[col + 128]);
    __syncthreads();
    sh[threadIdx.x] = q; __syncthreads();
    if (half == 0) atomicAdd(&sumsq[col], sh[col] + sh[col + 128]);
}

__global__ void bn_final_k(const float* __restrict__ sum, const float* __restrict__ sumsq,
                           const float* __restrict__ gamma, const float* __restrict__ beta,
                           float* __restrict__ scale, float* __restrict__ shift) {
    int t = threadIdx.x;
    if (t < DH) {
        const float inv_n = 1.0f / (float)N_NODES;
        float mu = sum[t] * inv_n;
        float var = sumsq[t] * inv_n - mu * mu;
        float is = rsqrtf(var + BN_EPS);
        float sc = gamma[t] * is;
        scale[t] = sc;
        shift[t] = beta[t] - mu * sc;
    }
}

// ---------------- final head: [N,128] @ Wr[128,2] + br -------------------------
__global__ void __launch_bounds__(256)
wr_k(const float* __restrict__ HC, const float* __restrict__ Wr,
     const float* __restrict__ br, float* __restrict__ out) {
    int w = (blockIdx.x * blockDim.x + threadIdx.x) >> 5;
    if (w >= N_NODES) return;
    int lane = threadIdx.x & 31;
    float4 v = ((const float4*)(HC + (size_t)w * DH))[lane];
    const float4* Wr4 = (const float4*)Wr;
    float4 a = Wr4[lane * 2];       // {Wr[4l][0], Wr[4l][1], Wr[4l+1][0], Wr[4l+1][1]}
    float4 b = Wr4[lane * 2 + 1];   // {Wr[4l+2][0], Wr[4l+2][1], Wr[4l+3][0], Wr[4l+3][1]}
    float s0 = v.x * a.x + v.y * a.z + v.z * b.x + v.w * b.z;
    float s1 = v.x * a.y + v.y * a.w + v.z * b.y + v.w * b.w;
    #pragma unroll
    for (int o = 16; o; o >>= 1) {
        s0 += __shfl_xor_sync(0xffffffffu, s0, o);
        s1 += __shfl_xor_sync(0xffffffffu, s1, o);
    }
    if (lane == 0) {
        out[(size_t)w * 2 + 0] = s0 + br[0];
        out[(size_t)w * 2 + 1] = s1 + br[1];
    }
}

// ---------------- launch ----------------
extern "C" void kernel_launch(void* const* d_in, const int* in_sizes, int n_in,
                              void* d_out, int out_size) {
    const float* x     = (const float*)d_in[0];
    const int*   ei    = (const int*)d_in[1];
    const float* W1    = (const float*)d_in[2];
    const float* b1    = (const float*)d_in[3];
    const float* W2    = (const float*)d_in[4];
    const float* b2    = (const float*)d_in[5];
    const float* W3    = (const float*)d_in[6];
    const float* b3    = (const float*)d_in[7];
    const float* gamma = (const float*)d_in[8];
    const float* beta  = (const float*)d_in[9];
    const float* Wc    = (const float*)d_in[10];
    const float* bc    = (const float*)d_in[11];
    const float* Wr    = (const float*)d_in[12];
    const float* br    = (const float*)d_in[13];

    const int* src = ei;
    const int* dst = ei + E_EDGES;

    float *bufH, *bufA, *bufB, *deg, *dinv, *sum, *sumsq, *bnscale, *bnshift;
    cudaGetSymbolAddress((void**)&bufH, g_bufH);
    cudaGetSymbolAddress((void**)&bufA, g_bufA);
    cudaGetSymbolAddress((void**)&bufB, g_bufB);
    cudaGetSymbolAddress((void**)&deg, g_deg);
    cudaGetSymbolAddress((void**)&dinv, g_dinv);
    cudaGetSymbolAddress((void**)&sum, g_sum);
    cudaGetSymbolAddress((void**)&sumsq, g_sumsq);
    cudaGetSymbolAddress((void**)&bnscale, g_bnscale);
    cudaGetSymbolAddress((void**)&bnshift, g_bnshift);

    const int GEMM_BLOCKS = N_NODES / 32;      // 3125
    const int EDGE_BLOCKS = E_EDGES / 8;       // 200000 (warp per edge, 8 warps/block)

    init_deg_k<<<(N_NODES + 255) / 256, 256>>>(deg, sum, sumsq);
    count_deg_k<<<(E_EDGES + 255) / 256, 256>>>(dst, deg);
    dinv_k<<<(N_NODES + 255) / 256, 256>>>(deg, dinv);

    // layer 1: x -> bufA
    gemm128_k<0><<<GEMM_BLOCKS, 256>>>(x, W1, b1, bufH, bufA, dinv, nullptr, nullptr);
    edge_agg_k<<<EDGE_BLOCKS, 256>>>(src, dst, dinv, bufH, bufA);
    // layer 2: relu(bufA) -> bufB
    gemm128_k<1><<<GEMM_BLOCKS, 256>>>(bufA, W2, b2, bufH, bufB, dinv, nullptr, nullptr);
    edge_agg_k<<<EDGE_BLOCKS, 256>>>(src, dst, dinv, bufH, bufB);
    // layer 3: relu(bufB) -> bufA
    gemm128_k<1><<<GEMM_BLOCKS, 256>>>(bufB, W3, b3, bufH, bufA, dinv, nullptr, nullptr);
    edge_agg_k<<<EDGE_BLOCKS, 256>>>(src, dst, dinv, bufH, bufA);

    // batchnorm over relu(bufA)
    bn_stats_k<<<125, 256>>>(bufA, sum, sumsq);
    bn_final_k<<<1, 128>>>(sum, sumsq, gamma, beta, bnscale, bnshift);

    // classifier: relu(bn(relu(bufA)) @ Wc + bc) -> bufB
    gemm128_k<2><<<GEMM_BLOCKS, 256>>>(bufA, Wc, bc, nullptr, bufB, nullptr, bnscale, bnshift);
    // head: bufB @ Wr + br -> out
    wr_k<<<(N_NODES * 32 + 255) / 256, 256>>>(bufB, Wr, br, (float*)d_out);
}

// round 3
// speedup vs baseline: 1.3750x; 1.3750x over previous
#include <cuda_runtime.h>
#include <cstdint>

#define N_NODES 100000
#define E_EDGES 1600000
#define DH 128
#define BN_EPS 1e-5f
#define SCAN_T 1024

// ---------------- scratch (static device memory; no allocations) ----------------
__device__ float g_bufH[(size_t)N_NODES * DH];   // H' = (A@W) * dinv[row]
__device__ float g_bufA[(size_t)N_NODES * DH];
__device__ float g_bufB[(size_t)N_NODES * DH];
__device__ int   g_cnt[N_NODES];
__device__ int   g_rowptr[N_NODES + 1];
__device__ int   g_cursor[N_NODES];
__device__ int   g_srcs[E_EDGES];
__device__ float g_dinv[N_NODES];
__device__ float g_sum[DH];
__device__ float g_sumsq[DH];
__device__ float g_bnscale[DH];
__device__ float g_bnshift[DH];

// ---------------- CSR build ----------------
__global__ void init_k(int* __restrict__ cnt, float* __restrict__ sum,
                       float* __restrict__ sumsq) {
    int i = blockIdx.x * blockDim.x + threadIdx.x;
    if (i < N_NODES) cnt[i] = 0;
    if (i < DH) { sum[i] = 0.f; sumsq[i] = 0.f; }
}

__global__ void count_k(const int* __restrict__ dst, int* __restrict__ cnt) {
    int e = blockIdx.x * blockDim.x + threadIdx.x;
    if (e < E_EDGES) atomicAdd(&cnt[dst[e]], 1);
}

// single-block scan: row_ptr, cursor copy, dinv = rsqrt(cnt+1)
__global__ void __launch_bounds__(SCAN_T)
scan_k(const int* __restrict__ cnt, int* __restrict__ row_ptr,
       int* __restrict__ cursor, float* __restrict__ dinv) {
    __shared__ int sh[SCAN_T];
    const int t = threadIdx.x;
    const int chunk = (N_NODES + SCAN_T - 1) / SCAN_T;
    const int beg = t * chunk;
    const int end = min(beg + chunk, N_NODES);
    int s = 0;
    for (int i = beg; i < end; ++i) s += cnt[i];
    sh[t] = s;
    __syncthreads();
    for (int o = 1; o < SCAN_T; o <<= 1) {
        int u = (t >= o) ? sh[t - o] : 0;
        __syncthreads();
        sh[t] += u;
        __syncthreads();
    }
    int running = sh[t] - s;   // exclusive prefix
    for (int i = beg; i < end; ++i) {
        row_ptr[i] = running;
        cursor[i] = running;
        dinv[i] = rsqrtf((float)cnt[i] + 1.0f);
        running += cnt[i];
    }
    if (t == SCAN_T - 1) row_ptr[N_NODES] = E_EDGES;
}

__global__ void scatter_k(const int* __restrict__ src, const int* __restrict__ dst,
                          int* __restrict__ cursor, int* __restrict__ srcs) {
    int e = blockIdx.x * blockDim.x + threadIdx.x;
    if (e < E_EDGES) {
        int pos = atomicAdd(&cursor[dst[e]], 1);
        srcs[pos] = src[e];
    }
}

// ---------------- GEMM: [N,128] @ [128,128], fused transforms ----------------
// MODE 0: H' = (A @ W) * dinv[row]              (feeds aggregation)
// MODE 2: Out = relu((bn(A)) @ W + b)           (classifier; A already relu'd)
template <int MODE>
__global__ void __launch_bounds__(256)
gemm128_k(const float* __restrict__ A, const float* __restrict__ W,
          const float* __restrict__ bias, float* __restrict__ Out,
          const float* __restrict__ dinv,
          const float* __restrict__ bnscale, const float* __restrict__ bnshift) {
    __shared__ float Ws[32][DH];
    __shared__ float As[32][36];

    const int tid = threadIdx.x;
    const int row0 = blockIdx.x * 32;
    const int ty = tid >> 5;   // 0..7  -> 4 rows each
    const int tx = tid & 31;   // 0..31 -> 4 cols each

    float acc[4][4] = {};
    const float4* W4 = (const float4*)W;
    const float4* A4 = (const float4*)A;

    for (int kt = 0; kt < 4; ++kt) {
        // A tile 32x32 via float4: 256 threads x 1 float4
        {
            int r = tid >> 3, k4 = tid & 7;      // k4: 0..7 -> cols k4*4..
            int gk4 = kt * 8 + k4;
            float4 v = A4[(size_t)(row0 + r) * 32 + gk4];
            if (MODE == 2) {
                float4 sc = ((const float4*)bnscale)[gk4];
                float4 sf = ((const float4*)bnshift)[gk4];
                v.x = v.x * sc.x + sf.x; v.y = v.y * sc.y + sf.y;
                v.z = v.z * sc.z + sf.z; v.w = v.w * sc.w + sf.w;
            }
            *(float4*)&As[r][k4 * 4] = v;
        }
        // W tile 32x128 via float4
        #pragma unroll
        for (int i = 0; i < 4; ++i) {
            int idx = tid + i * 256;
            int kr = idx >> 5, n4 = idx & 31;
            float4 w = W4[(size_t)(kt * 32 + kr) * 32 + n4];
            *(float4*)&Ws[kr][n4 * 4] = w;
        }
        __syncthreads();

        #pragma unroll
        for (int k = 0; k < 32; ++k) {
            float a0 = As[ty * 4 + 0][k];
            float a1 = As[ty * 4 + 1][k];
            float a2 = As[ty * 4 + 2][k];
            float a3 = As[ty * 4 + 3][k];
            float4 b = *(float4*)&Ws[k][tx * 4];
            acc[0][0] += a0 * b.x; acc[0][1] += a0 * b.y; acc[0][2] += a0 * b.z; acc[0][3] += a0 * b.w;
            acc[1][0] += a1 * b.x; acc[1][1] += a1 * b.y; acc[1][2] += a1 * b.z; acc[1][3] += a1 * b.w;
            acc[2][0] += a2 * b.x; acc[2][1] += a2 * b.y; acc[2][2] += a2 * b.z; acc[2][3] += a2 * b.w;
            acc[3][0] += a3 * b.x; acc[3][1] += a3 * b.y; acc[3][2] += a3 * b.z; acc[3][3] += a3 * b.w;
        }
        __syncthreads();
    }

    #pragma unroll
    for (int i = 0; i < 4; ++i) {
        int r = row0 + ty * 4 + i;
        if (MODE == 0) {
            float sc = dinv[r];
            float4 o = make_float4(acc[i][0] * sc, acc[i][1] * sc,
                                   acc[i][2] * sc, acc[i][3] * sc);
            *(float4*)&Out[(size_t)r * DH + tx * 4] = o;
        } else {
            float4 bv = *(const float4*)&bias[tx * 4];
            float4 o = make_float4(fmaxf(acc[i][0] + bv.x, 0.f),
                                   fmaxf(acc[i][1] + bv.y, 0.f),
                                   fmaxf(acc[i][2] + bv.z, 0.f),
                                   fmaxf(acc[i][3] + bv.w, 0.f));
            *(float4*)&Out[(size_t)r * DH + tx * 4] = o;
        }
    }
}

// ---------------- CSR aggregation: warp per node, pure float4 adds ----------
// Out[d] = relu( dinv[d] * (H'[d] + sum_{e in row d} H'[srcs[e]]) + bias )
__global__ void __launch_bounds__(256)
agg_k(const int* __restrict__ row_ptr, const int* __restrict__ srcs,
      const float* __restrict__ dinv, const float* __restrict__ Hp,
      const float* __restrict__ bias, float* __restrict__ Out) {
    int node = (blockIdx.x * blockDim.x + threadIdx.x) >> 5;
    if (node >= N_NODES) return;
    const int lane = threadIdx.x & 31;
    const float4* H4 = (const float4*)Hp;

    float4 acc = H4[(size_t)node * 32 + lane];     // self-loop term
    float4 acc2 = make_float4(0.f, 0.f, 0.f, 0.f);

    int e = row_ptr[node];
    const int end = row_ptr[node + 1];
    for (; e + 2 <= end; e += 2) {
        int s0 = __ldg(&srcs[e]);
        int s1 = __ldg(&srcs[e + 1]);
        float4 v0 = H4[(size_t)s0 * 32 + lane];
        float4 v1 = H4[(size_t)s1 * 32 + lane];
        acc.x += v0.x; acc.y += v0.y; acc.z += v0.z; acc.w += v0.w;
        acc2.x += v1.x; acc2.y += v1.y; acc2.z += v1.z; acc2.w += v1.w;
    }
    if (e < end) {
        int s0 = __ldg(&srcs[e]);
        float4 v0 = H4[(size_t)s0 * 32 + lane];
        acc.x += v0.x; acc.y += v0.y; acc.z += v0.z; acc.w += v0.w;
    }
    acc.x += acc2.x; acc.y += acc2.y; acc.z += acc2.z; acc.w += acc2.w;

    const float dv = dinv[node];
    float4 b = ((const float4*)bias)[lane];
    float4 o = make_float4(fmaxf(acc.x * dv + b.x, 0.f),
                           fmaxf(acc.y * dv + b.y, 0.f),
                           fmaxf(acc.z * dv + b.z, 0.f),
                           fmaxf(acc.w * dv + b.w, 0.f));
    ((float4*)Out)[(size_t)node * 32 + lane] = o;
}

// ---------------- BN statistics (input already relu'd) -----------------------
__global__ void __launch_bounds__(256)
bn_stats_k(const float* __restrict__ A, float* __restrict__ sum,
           float* __restrict__ sumsq) {
    const int col = threadIdx.x & 127;
    const int half = threadIdx.x >> 7;
    const int r0 = blockIdx.x * 800;
    float s = 0.f, q = 0.f;
    for (int r = r0 + half; r < r0 + 800; r += 2) {
        float v = A[(size_t)r * DH + col];
        s += v; q += v * v;
    }
    __shared__ float sh[256];
    sh[threadIdx.x] = s; __syncthreads();
    if (half == 0) atomicAdd(&sum[col], sh[col] + sh[col + 128]);
    __syncthreads();
    sh[threadIdx.x] = q; __syncthreads();
    if (half == 0) atomicAdd(&sumsq[col], sh[col] + sh[col + 128]);
}

__global__ void bn_final_k(const float* __restrict__ sum, const float* __restrict__ sumsq,
                           const float* __restrict__ gamma, const float* __restrict__ beta,
                           float* __restrict__ scale, float* __restrict__ shift) {
    int t = threadIdx.x;
    if (t < DH) {
        const float inv_n = 1.0f / (float)N_NODES;
        float mu = sum[t] * inv_n;
        float var = sumsq[t] * inv_n - mu * mu;
        float is = rsqrtf(var + BN_EPS);
        float sc = gamma[t] * is;
        scale[t] = sc;
        shift[t] = beta[t] - mu * sc;
    }
}

// ---------------- final head: [N,128] @ Wr[128,2] + br -------------------------
__global__ void __launch_bounds__(256)
wr_k(const float* __restrict__ HC, const float* __restrict__ Wr,
     const float* __restrict__ br, float* __restrict__ out) {
    int w = (blockIdx.x * blockDim.x + threadIdx.x) >> 5;
    if (w >= N_NODES) return;
    int lane = threadIdx.x & 31;
    float4 v = ((const float4*)(HC + (size_t)w * DH))[lane];
    const float4* Wr4 = (const float4*)Wr;
    float4 a = Wr4[lane * 2];
    float4 b = Wr4[lane * 2 + 1];
    float s0 = v.x * a.x + v.y * a.z + v.z * b.x + v.w * b.z;
    float s1 = v.x * a.y + v.y * a.w + v.z * b.y + v.w * b.w;
    #pragma unroll
    for (int o = 16; o; o >>= 1) {
        s0 += __shfl_xor_sync(0xffffffffu, s0, o);
        s1 += __shfl_xor_sync(0xffffffffu, s1, o);
    }
    if (lane == 0) {
        out[(size_t)w * 2 + 0] = s0 + br[0];
        out[(size_t)w * 2 + 1] = s1 + br[1];
    }
}

// ---------------- launch ----------------
extern "C" void kernel_launch(void* const* d_in, const int* in_sizes, int n_in,
                              void* d_out, int out_size) {
    const float* x     = (const float*)d_in[0];
    const int*   ei    = (const int*)d_in[1];
    const float* W1    = (const float*)d_in[2];
    const float* b1    = (const float*)d_in[3];
    const float* W2    = (const float*)d_in[4];
    const float* b2    = (const float*)d_in[5];
    const float* W3    = (const float*)d_in[6];
    const float* b3    = (const float*)d_in[7];
    const float* gamma = (const float*)d_in[8];
    const float* beta  = (const float*)d_in[9];
    const float* Wc    = (const float*)d_in[10];
    const float* bc    = (const float*)d_in[11];
    const float* Wr    = (const float*)d_in[12];
    const float* br    = (const float*)d_in[13];

    const int* src = ei;
    const int* dst = ei + E_EDGES;

    float *bufH, *bufA, *bufB, *dinv, *sum, *sumsq, *bnscale, *bnshift;
    int *cnt, *rowptr, *cursor, *srcs;
    cudaGetSymbolAddress((void**)&bufH, g_bufH);
    cudaGetSymbolAddress((void**)&bufA, g_bufA);
    cudaGetSymbolAddress((void**)&bufB, g_bufB);
    cudaGetSymbolAddress((void**)&cnt, g_cnt);
    cudaGetSymbolAddress((void**)&rowptr, g_rowptr);
    cudaGetSymbolAddress((void**)&cursor, g_cursor);
    cudaGetSymbolAddress((void**)&srcs, g_srcs);
    cudaGetSymbolAddress((void**)&dinv, g_dinv);
    cudaGetSymbolAddress((void**)&sum, g_sum);
    cudaGetSymbolAddress((void**)&sumsq, g_sumsq);
    cudaGetSymbolAddress((void**)&bnscale, g_bnscale);
    cudaGetSymbolAddress((void**)&bnshift, g_bnshift);

    const int GEMM_BLOCKS = N_NODES / 32;              // 3125
    const int AGG_BLOCKS = (N_NODES * 32 + 255) / 256; // warp per node

    // CSR build + dinv
    init_k<<<(N_NODES + 255) / 256, 256>>>(cnt, sum, sumsq);
    count_k<<<(E_EDGES + 255) / 256, 256>>>(dst, cnt);
    scan_k<<<1, SCAN_T>>>(cnt, rowptr, cursor, dinv);
    scatter_k<<<(E_EDGES + 255) / 256, 256>>>(src, dst, cursor, srcs);

    // layer 1
    gemm128_k<0><<<GEMM_BLOCKS, 256>>>(x, W1, nullptr, bufH, dinv, nullptr, nullptr);
    agg_k<<<AGG_BLOCKS, 256>>>(rowptr, srcs, dinv, bufH, b1, bufA);
    // layer 2 (bufA already relu'd)
    gemm128_k<0><<<GEMM_BLOCKS, 256>>>(bufA, W2, nullptr, bufH, dinv, nullptr, nullptr);
    agg_k<<<AGG_BLOCKS, 256>>>(rowptr, srcs, dinv, bufH, b2, bufB);
    // layer 3
    gemm128_k<0><<<GEMM_BLOCKS, 256>>>(bufB, W3, nullptr, bufH, dinv, nullptr, nullptr);
    agg_k<<<AGG_BLOCKS, 256>>>(rowptr, srcs, dinv, bufH, b3, bufA);

    // batchnorm (bufA already relu'd)
    bn_stats_k<<<125, 256>>>(bufA, sum, sumsq);
    bn_final_k<<<1, 128>>>(sum, sumsq, gamma, beta, bnscale, bnshift);

    // classifier + head
    gemm128_k<2><<<GEMM_BLOCKS, 256>>>(bufA, Wc, bc, bufB, nullptr, bnscale, bnshift);
    wr_k<<<(N_NODES * 32 + 255) / 256, 256>>>(bufB, Wr, br, (float*)d_out);
}